// round 10
// baseline (speedup 1.0000x reference)
#include <cuda_runtime.h>

// out[b, q, j] = float( max(0, q - 127) + j )   for B=8, Q=4096, K=64.
//
// Derivation: reference masks local window [q-127, q] to +inf, future
// (k>q) to -inf, then stable top_k(64) (lowest index wins ties) -> always
// the 64 lowest window indices = max(0,q-127)+0..63. Input I is
// irrelevant; output buffer dtype is float32 (confirmed R1/R2).
//
// Converged model (R2-R9): latency-floor kernel. Requirements:
//   - 524,288 threads, one STG.128 each (max warp parallelism; every
//     fatter-thread variant regressed: R3/R4/R9).
//   - fewer CTAs at constant threads shortens the scheduler ramp
//     (R7 2048x256 = 4.70us -> R8 512x1024 = 4.42us).
// Final probe: midpoint 1024 CTAs x 512 threads (4 CTAs/SM residency may
// fill the chip faster during ramp). If >= R8, R8 is final.

__global__ void __launch_bounds__(512)
TokenSelector_17755394801797_kernel(float4* __restrict__ out) {
    int idx = blockIdx.x * 512 + threadIdx.x;   // 0..524287, one float4 each
    int lin = idx << 2;                         // first element index
    int j   = lin & 63;                         // within-row position
    int q   = (lin >> 6) & 4095;                // query row
    int start = max(q - 127, 0);
    float base = (float)(start + j);

    float4 v;
    v.x = base;
    v.y = base + 1.0f;
    v.z = base + 2.0f;
    v.w = base + 3.0f;
    out[idx] = v;
}

extern "C" void kernel_launch(void* const* d_in, const int* in_sizes, int n_in,
                              void* d_out, int out_size) {
    (void)d_in; (void)in_sizes; (void)n_in; (void)out_size;
    // 2,097,152 floats / 4 per thread / 512 threads = 1024 blocks, exact.
    TokenSelector_17755394801797_kernel<<<1024, 512>>>((float4*)d_out);
}